// round 15
// baseline (speedup 1.0000x reference)
#include <cuda_runtime.h>
#include <cuda_fp16.h>
#include <mma.h>
#include <math.h>
#include <cstdint>

using namespace nvcuda;

#define N_NODES 100000
#define N_EDGES 1600000
#define N_PAD 100096                          // 782*128
#define N_TILES 782
#define NB_SCAN ((N_NODES + 1023) / 1024)     // 98

#define TS 136                                // smem A/W tile stride (fp16 elems)
#define T2S 80                                // smem W2 tile stride (160B rows)
#define TILE_ELEMS (128 * TS)                 // 17408

// gemm1 smem: AH, WH0, WH1 (3 x 128x136 fp16) + 64KB fp32 staging
#define GEMM1_SMEM (3 * TILE_ELEMS * 2 + 16 * 1024 * 4)
// fused smem: AH (128x136 fp16) + W2H (128x80 fp16)
#define FUSED_SMEM ((TILE_ELEMS + 128 * T2S) * 2)

// -------- scratch (static __device__ globals; no runtime alloc) ----------
__device__ int    g_is64;
__device__ int    g_degi[N_NODES];
__device__ int    g_cursor[N_NODES];          // initialized to rowstart by k_scan
__device__ int    g_rowstart[N_NODES + 1];
__device__ unsigned long long g_part[NB_SCAN];// lookback: (state<<32)|value
__device__ int    g_csrc[N_EDGES];
__device__ __half g_y1h[(size_t)N_PAD * 128]; // x @ Wl1  (fp16)
__device__ __half g_yrh[(size_t)N_PAD * 128]; // x @ Wr1  (fp16)
__device__ __half g_pqh[(size_t)N_PAD * 80];  // [p(40) | q(40)] per node (fp16)
// precomputed fp16 weights
__device__ __half g_wl1h[16384];
__device__ __half g_wr1h[16384];
__device__ __half g_w2h[10240];               // [Wl2|Wr2] 128x80

// ---------- prep: zero degi + lookback state, dtype detect, weight convert ----------
__global__ __launch_bounds__(1024) void k_prep(
    const float* __restrict__ Wl1, const float* __restrict__ Wr1,
    const float* __restrict__ Wl2, const float* __restrict__ Wr2,
    const int* __restrict__ ei32) {
    int i = blockIdx.x * 1024 + threadIdx.x;
    if (i < N_NODES) g_degi[i] = 0;
    if (i < NB_SCAN) g_part[i] = 0ULL;
    if (i == 0) g_rowstart[N_NODES] = N_EDGES;

    if (blockIdx.x == 0) {
        __shared__ int nz;
        if (threadIdx.x == 0) nz = 0;
        __syncthreads();
        if (threadIdx.x < 256 && ei32[2 * threadIdx.x + 1] != 0) atomicAdd(&nz, 1);
        __syncthreads();
        if (threadIdx.x == 0) g_is64 = (nz == 0) ? 1 : 0;

        for (int k = threadIdx.x; k < 16384; k += 1024) {
            g_wl1h[k] = __float2half_rn(Wl1[k]);
            g_wr1h[k] = __float2half_rn(Wr1[k]);
        }
        for (int k = threadIdx.x; k < 10240; k += 1024) {
            int r = k / 80, j = k % 80;
            float v = (j < 40) ? Wl2[r * 40 + j] : Wr2[r * 40 + (j - 40)];
            g_w2h[k] = __float2half_rn(v);
        }
    }
}

// -------------------- CSR build --------------------

__global__ void k_count(const void* __restrict__ ei) {
    int idx = blockIdx.x * blockDim.x + threadIdx.x;
    int stride = gridDim.x * blockDim.x;
    if (g_is64) {
        const longlong2* p = (const longlong2*)((const long long*)ei + N_EDGES);
        for (int i = idx; i < N_EDGES / 2; i += stride) {
            longlong2 v = p[i];
            atomicAdd(&g_degi[(int)v.x], 1);
            atomicAdd(&g_degi[(int)v.y], 1);
        }
    } else {
        const int4* p = (const int4*)((const int*)ei + N_EDGES);
        for (int i = idx; i < N_EDGES / 4; i += stride) {
            int4 v = p[i];
            atomicAdd(&g_degi[v.x], 1);
            atomicAdd(&g_degi[v.y], 1);
            atomicAdd(&g_degi[v.z], 1);
            atomicAdd(&g_degi[v.w], 1);
        }
    }
}

// single-launch decoupled-lookback exclusive scan; writes rowstart AND cursor.
// 98 blocks <= 148 SMs: all co-resident, spin cannot deadlock.
__global__ __launch_bounds__(1024) void k_scan() {
    __shared__ int wsum[32];
    __shared__ int s_total, s_prefix;
    int bid = blockIdx.x;
    int i = bid * 1024 + threadIdx.x;
    int lane = threadIdx.x & 31, wid = threadIdx.x >> 5;
    int v = (i < N_NODES) ? g_degi[i] : 0;
    int pre = v;
#pragma unroll
    for (int o = 1; o < 32; o <<= 1) {
        int t = __shfl_up_sync(0xffffffffu, pre, o);
        if (lane >= o) pre += t;
    }
    if (lane == 31) wsum[wid] = pre;
    __syncthreads();
    if (wid == 0) {
        int w = wsum[lane];
        int p = w;
#pragma unroll
        for (int o = 1; o < 32; o <<= 1) {
            int t = __shfl_up_sync(0xffffffffu, p, o);
            if (lane >= o) p += t;
        }
        wsum[lane] = p - w;
        if (lane == 31) s_total = p;
    }
    __syncthreads();

    if (threadIdx.x == 0) {
        int total = s_total;
        if (bid == 0) {
            atomicExch(&g_part[0], (2ULL << 32) | (unsigned)total);
            s_prefix = 0;
        } else {
            atomicExch(&g_part[bid], (1ULL << 32) | (unsigned)total);
            int run = 0;
            int j = bid - 1;
            while (true) {
                unsigned long long w = atomicAdd(&g_part[j], 0ULL);
                unsigned st = (unsigned)(w >> 32);
                if (st == 0) continue;               // predecessor not published yet
                run += (int)(w & 0xFFFFFFFFULL);
                if (st == 2) break;                  // inclusive prefix found
                j--;
            }
            s_prefix = run;
            atomicExch(&g_part[bid], (2ULL << 32) | (unsigned)(run + total));
        }
    }
    __syncthreads();

    if (i < N_NODES) {
        int base = s_prefix + pre - v + wsum[wid];
        g_rowstart[i] = base;
        g_cursor[i] = base;
    }
}

__global__ void k_fill(const void* __restrict__ ei) {
    int idx = blockIdx.x * blockDim.x + threadIdx.x;
    int stride = gridDim.x * blockDim.x;
    if (g_is64) {
        const longlong2* ps = (const longlong2*)ei;
        const longlong2* pd = (const longlong2*)((const long long*)ei + N_EDGES);
        for (int i = idx; i < N_EDGES / 2; i += stride) {
            longlong2 s = ps[i];
            longlong2 d = pd[i];
            g_csrc[atomicAdd(&g_cursor[(int)d.x], 1)] = (int)s.x;
            g_csrc[atomicAdd(&g_cursor[(int)d.y], 1)] = (int)s.y;
        }
    } else {
        const int4* ps = (const int4*)ei;
        const int4* pd = (const int4*)((const int*)ei + N_EDGES);
        for (int i = idx; i < N_EDGES / 4; i += stride) {
            int4 s = ps[i];
            int4 d = pd[i];
            g_csrc[atomicAdd(&g_cursor[d.x], 1)] = s.x;
            g_csrc[atomicAdd(&g_cursor[d.y], 1)] = s.y;
            g_csrc[atomicAdd(&g_cursor[d.z], 1)] = s.z;
            g_csrc[atomicAdd(&g_cursor[d.w], 1)] = s.w;
        }
    }
}

// ============ helpers ============

// convert 128x128 fp32 (row stride 128, rows clamped) into a single fp16 tile
template <int NTHREADS>
__device__ __forceinline__ void conv_tile_h(const float* __restrict__ src, int row0,
                                            __half* H, int tid) {
    for (int g = tid; g < 4096; g += NTHREADS) {
        int row = g >> 5, c4 = g & 31;
        int r = row0 + row;
        if (r >= N_NODES) r = N_NODES - 1;
        float4 v = ((const float4*)(src + (size_t)r * 128))[c4];
        __half2 h0 = __floats2half2_rn(v.x, v.y);
        __half2 h1 = __floats2half2_rn(v.z, v.w);
        *(uint2*)(H + row * TS + c4 * 4) = make_uint2(*(uint32_t*)&h0, *(uint32_t*)&h1);
    }
}

// ============ GEMM 1 (persistent, fp16 single-pass): y1 = x@Wl1, yr = x@Wr1 ============

__global__ __launch_bounds__(512) void k_gemm1(const float* __restrict__ x) {
    extern __shared__ __half sm[];
    __half* AH  = sm;
    __half* WH0 = sm + TILE_ELEMS;
    __half* WH1 = sm + 2 * TILE_ELEMS;
    float* staging = (float*)(sm + 3 * TILE_ELEMS);

    int tid = threadIdx.x;
    int wid = tid >> 5, lane = tid & 31;

    // copy fp16 weights into padded smem ONCE (one uint4 = 8 halves)
    {
        const __half* srcs[2] = {g_wl1h, g_wr1h};
        __half* dsts[2] = {WH0, WH1};
#pragma unroll
        for (int tgt = 0; tgt < 2; tgt++) {
            const uint4* s = (const uint4*)srcs[tgt];
            for (int g = tid; g < 2048; g += 512) {   // 128 rows x 16 uint4
                int row = g >> 4, c = g & 15;
                *(uint4*)(dsts[tgt] + row * TS + c * 8) = s[row * 16 + c];
            }
        }
    }

    int out_sel = wid >> 3;          // 0: y1, 1: yr
    int w = wid & 7;
    int wm = w & 3;                  // rows wm*32
    int wn = w >> 2;                 // cols wn*64
    const __half* WH = out_sel ? WH1 : WH0;
    __half* dstbase = out_sel ? g_yrh : g_y1h;
    float* eb = staging + (size_t)wid * 1024;   // 16x64 fp32 per warp

    for (int tile = blockIdx.x; tile < N_TILES; tile += gridDim.x) {
        int node0 = tile * 128;
        conv_tile_h<512>(x, node0, AH, tid);
        __syncthreads();

        wmma::fragment<wmma::accumulator, 16, 16, 16, float> C[2][4];
#pragma unroll
        for (int i = 0; i < 2; i++)
#pragma unroll
            for (int j = 0; j < 4; j++) wmma::fill_fragment(C[i][j], 0.0f);

#pragma unroll
        for (int k0 = 0; k0 < 8; k0++) {
            wmma::fragment<wmma::matrix_a, 16, 16, 16, __half, wmma::row_major> ah[2];
#pragma unroll
            for (int i = 0; i < 2; i++)
                wmma::load_matrix_sync(ah[i], AH + (wm * 32 + i * 16) * TS + k0 * 16, TS);
#pragma unroll
            for (int j = 0; j < 4; j++) {
                wmma::fragment<wmma::matrix_b, 16, 16, 16, __half, wmma::row_major> bh;
                wmma::load_matrix_sync(bh, WH + (k0 * 16) * TS + wn * 64 + j * 16, TS);
#pragma unroll
                for (int i = 0; i < 2; i++)
                    wmma::mma_sync(C[i][j], ah[i], bh, C[i][j]);
            }
        }

        // epilogue: per warp stage 16x64 fp32 at a time, convert to fp16, store
#pragma unroll
        for (int i = 0; i < 2; i++) {
#pragma unroll
            for (int j = 0; j < 4; j++)
                wmma::store_matrix_sync(eb + j * 16, C[i][j], 64, wmma::mem_row_major);
            __syncwarp();
            for (int e = lane; e < 512; e += 32) {    // 16 rows x 32 half2
                int r = e >> 5, c2 = e & 31;
                float2 v = ((const float2*)eb)[e];
                __half2 hv = __floats2half2_rn(v.x, v.y);
                *(__half2*)(dstbase + (size_t)(node0 + wm * 32 + i * 16 + r) * 128
                            + wn * 64 + c2 * 2) = hv;
            }
            __syncwarp();
        }
        __syncthreads();   // A reads done before next tile's conv overwrites
    }
}

// ====== FUSED: h = relu(mean-gather(y1) + yr + b1)  ->  pq = h @ [Wl2|Wr2] ======

__global__ __launch_bounds__(512) void k_aggr_gemm2(const float* __restrict__ b1) {
    extern __shared__ __half sm[];
    __half* AH  = sm;
    __half* W2H = sm + TILE_ELEMS;

    int tid = threadIdx.x;
    int wid = tid >> 5, lane = tid & 31;
    int node0 = blockIdx.x * 128;

    // copy W2 fp16 (128x80) into smem
    {
        const uint4* sh = (const uint4*)g_w2h;
        for (int g = tid; g < 1280; g += 512) {   // 128 rows x 10 uint4
            int row = g / 10, c = g % 10;
            *(uint4*)(W2H + row * T2S + c * 8) = sh[row * 10 + c];
        }
    }

    // ---- Phase A: gather (y1 fp16) + relu, fp16 into smem ----
    float4 bb = *(const float4*)(b1 + lane * 4);
#pragma unroll
    for (int i = 0; i < 8; i++) {
        int nl = wid * 8 + i;
        int node = node0 + nl;
        float4 h4 = make_float4(0.f, 0.f, 0.f, 0.f);
        if (node < N_NODES) {
            int rs = g_rowstart[node], re = g_rowstart[node + 1];
            float4 acc = make_float4(0.f, 0.f, 0.f, 0.f);
            for (int i0 = rs; i0 < re; i0 += 32) {
                int nv = min(32, re - i0);
                int s = (lane < nv) ? g_csrc[i0 + lane] : 0;
                int j = 0;
                for (; j + 8 <= nv; j += 8) {
                    uint2 u[8];
#pragma unroll
                    for (int t = 0; t < 8; t++) {
                        int sj = __shfl_sync(0xffffffffu, s, j + t);
                        u[t] = *(const uint2*)(g_y1h + (size_t)sj * 128 + lane * 4);
                    }
#pragma unroll
                    for (int t = 0; t < 8; t++) {
                        float2 a = __half22float2(*(const __half2*)&u[t].x);
                        float2 b = __half22float2(*(const __half2*)&u[t].y);
                        acc.x += a.x; acc.y += a.y; acc.z += b.x; acc.w += b.y;
                    }
                }
                for (; j < nv; j++) {
                    int sj = __shfl_sync(0xffffffffu, s, j);
                    uint2 u = *(const uint2*)(g_y1h + (size_t)sj * 128 + lane * 4);
                    float2 a = __half22float2(*(const __half2*)&u.x);
                    float2 b = __half22float2(*(const __half2*)&u.y);
                    acc.x += a.x; acc.y += a.y; acc.z += b.x; acc.w += b.y;
                }
            }
            float inv = 1.0f / fmaxf((float)(re - rs), 1.0f);
            uint2 uyr = *(const uint2*)(g_yrh + (size_t)node * 128 + lane * 4);
            float2 ya = __half22float2(*(const __half2*)&uyr.x);
            float2 yb = __half22float2(*(const __half2*)&uyr.y);
            h4.x = fmaxf(acc.x * inv + ya.x + bb.x, 0.f);
            h4.y = fmaxf(acc.y * inv + ya.y + bb.y, 0.f);
            h4.z = fmaxf(acc.z * inv + yb.x + bb.z, 0.f);
            h4.w = fmaxf(acc.w * inv + yb.y + bb.w, 0.f);
        }
        __half2 h0 = __floats2half2_rn(h4.x, h4.y);
        __half2 h1 = __floats2half2_rn(h4.z, h4.w);
        *(uint2*)(AH + nl * TS + lane * 4) = make_uint2(*(uint32_t*)&h0, *(uint32_t*)&h1);
    }
    __syncthreads();

    // ---- Phase B: wmma gemm2 (single-pass fp16) ----
    int rblk = wid & 7;                 // rows rblk*16 .. +15
    int j0   = (wid < 8) ? 0 : 3;       // col frags {0,1,2} or {3,4}
    int nj   = (wid < 8) ? 3 : 2;

    wmma::fragment<wmma::accumulator, 16, 16, 16, float> C[3];
#pragma unroll
    for (int j = 0; j < 3; j++) wmma::fill_fragment(C[j], 0.0f);

#pragma unroll
    for (int k0 = 0; k0 < 8; k0++) {
        wmma::fragment<wmma::matrix_a, 16, 16, 16, __half, wmma::row_major> ah;
        wmma::load_matrix_sync(ah, AH + (rblk * 16) * TS + k0 * 16, TS);
        for (int j = 0; j < nj; j++) {
            wmma::fragment<wmma::matrix_b, 16, 16, 16, __half, wmma::row_major> bh;
            wmma::load_matrix_sync(bh, W2H + (k0 * 16) * T2S + (j0 + j) * 16, T2S);
            wmma::mma_sync(C[j], ah, bh, C[j]);
        }
    }
    __syncthreads();   // AH/W2H reads done -> reuse as fp32 staging

    // ---- epilogue: stage fp32 pq (128x80) in smem, convert to fp16 ----
    float* stage = (float*)sm;
    for (int j = 0; j < nj; j++)
        wmma::store_matrix_sync(stage + (rblk * 16) * 80 + (j0 + j) * 16, C[j],
                                80, wmma::mem_row_major);
    __syncthreads();
    for (int g = tid; g < 5120; g += 512) {   // 128 rows x 40 half2
        int row = g / 40, c2 = g % 40;
        float2 v = ((const float2*)stage)[g];
        __half2 hv = __floats2half2_rn(v.x, v.y);
        *(__half2*)(g_pqh + (size_t)(node0 + row) * 80 + c2 * 2) = hv;
    }
}

// ---------- layer-2 aggregation + bias + log_softmax ----------

__global__ void k_final(const float* __restrict__ b2, float* __restrict__ out) {
    int warp = (blockIdx.x * blockDim.x + threadIdx.x) >> 5;
    if (warp >= N_NODES) return;
    int lane = threadIdx.x & 31;
    int g  = lane / 10;          // 0,1,2 (lanes 30,31 idle)
    int gl = lane % 10;
    bool active = lane < 30;
    int rs = g_rowstart[warp], re = g_rowstart[warp + 1];
    float acc[4] = {0.f, 0.f, 0.f, 0.f};

    for (int i0 = rs; i0 < re; i0 += 32) {
        int nv = min(32, re - i0);
        int s = (lane < nv) ? g_csrc[i0 + lane] : 0;
        for (int j = 0; j < nv; j += 6) {
            int e0 = j + g, e1 = j + 3 + g;
            int src0 = __shfl_sync(0xffffffffu, s, (e0 < nv) ? e0 : 0);
            int src1 = __shfl_sync(0xffffffffu, s, (e1 < nv) ? e1 : 0);
            bool v0 = active && (e0 < nv);
            bool v1 = active && (e1 < nv);
            uint2 u0 = v0 ? *(const uint2*)(g_pqh + (size_t)src0 * 80 + gl * 4)
                          : make_uint2(0u, 0u);
            uint2 u1 = v1 ? *(const uint2*)(g_pqh + (size_t)src1 * 80 + gl * 4)
                          : make_uint2(0u, 0u);
            float2 a0 = __half22float2(*(const __half2*)&u0.x);
            float2 b0 = __half22float2(*(const __half2*)&u0.y);
            float2 a1 = __half22float2(*(const __half2*)&u1.x);
            float2 b1 = __half22float2(*(const __half2*)&u1.y);
            acc[0] += a0.x + a1.x;
            acc[1] += a0.y + a1.y;
            acc[2] += b0.x + b1.x;
            acc[3] += b0.y + b1.y;
        }
    }

#pragma unroll
    for (int k = 0; k < 4; k++) {
        float t1 = __shfl_sync(0xffffffffu, acc[k], (lane + 10) & 31);
        float t2 = __shfl_sync(0xffffffffu, acc[k], (lane + 20) & 31);
        acc[k] += t1 + t2;           // valid for lane < 10
    }

    float inv = 1.0f / fmaxf((float)(re - rs), 1.0f);
    float v0f, v1f, v2f, v3f;
    if (lane < 10) {
        uint2 uq = *(const uint2*)(g_pqh + (size_t)warp * 80 + 40 + gl * 4);
        float2 qa = __half22float2(*(const __half2*)&uq.x);
        float2 qb = __half22float2(*(const __half2*)&uq.y);
        float4 bbv = *(const float4*)(b2 + gl * 4);
        v0f = acc[0] * inv + bbv.x + qa.x;
        v1f = acc[1] * inv + bbv.y + qa.y;
        v2f = acc[2] * inv + bbv.z + qb.x;
        v3f = acc[3] * inv + bbv.w + qb.y;
    } else {
        v0f = v1f = v2f = v3f = -INFINITY;
    }

    float mx = fmaxf(fmaxf(v0f, v1f), fmaxf(v2f, v3f));
#pragma unroll
    for (int o = 16; o; o >>= 1) mx = fmaxf(mx, __shfl_xor_sync(0xffffffffu, mx, o));
    float se = 0.f;
    if (lane < 10)
        se = expf(v0f - mx) + expf(v1f - mx) + expf(v2f - mx) + expf(v3f - mx);
#pragma unroll
    for (int o = 16; o; o >>= 1) se += __shfl_xor_sync(0xffffffffu, se, o);
    float lse = logf(se);

    if (lane < 10) {
        float4 o4 = make_float4(v0f - mx - lse, v1f - mx - lse,
                                v2f - mx - lse, v3f - mx - lse);
        *(float4*)(out + (size_t)warp * 40 + gl * 4) = o4;
    }
}

// -------------------- launch --------------------

extern "C" void kernel_launch(void* const* d_in, const int* in_sizes, int n_in,
                              void* d_out, int out_size) {
    const float* x       = (const float*)d_in[0];
    const void*  ei      = d_in[1];
    const float* Wl1     = (const float*)d_in[2];
    const float* b1      = (const float*)d_in[3];
    const float* Wr1     = (const float*)d_in[4];
    const float* Wl2     = (const float*)d_in[5];
    const float* b2      = (const float*)d_in[6];
    const float* Wr2     = (const float*)d_in[7];
    float* out           = (float*)d_out;

    cudaFuncSetAttribute(k_gemm1, cudaFuncAttributeMaxDynamicSharedMemorySize, GEMM1_SMEM);
    cudaFuncSetAttribute(k_aggr_gemm2, cudaFuncAttributeMaxDynamicSharedMemorySize, FUSED_SMEM);

    // side stream + fork/join events (created once; deterministic work per call)
    static cudaStream_t s2 = nullptr;
    static cudaEvent_t ev_fork = nullptr, ev_join = nullptr;
    if (!s2) {
        cudaStreamCreateWithFlags(&s2, cudaStreamNonBlocking);
        cudaEventCreateWithFlags(&ev_fork, cudaEventDisableTiming);
        cudaEventCreateWithFlags(&ev_join, cudaEventDisableTiming);
    }

    // prep: zero degi + lookback state, dtype detect, fp16 weight convert
    k_prep<<<NB_SCAN, 1024>>>(Wl1, Wr1, Wl2, Wr2, (const int*)ei);

    // fork: gemm1 depends only on x + prep — run it alongside the CSR build
    cudaEventRecord(ev_fork, 0);
    cudaStreamWaitEvent(s2, ev_fork, 0);
    k_gemm1<<<148, 512, GEMM1_SMEM, s2>>>(x);
    cudaEventRecord(ev_join, s2);

    // main stream: CSR build chain
    k_count<<<1024, 256>>>(ei);
    k_scan<<<NB_SCAN, 1024>>>();
    k_fill<<<1024, 256>>>(ei);

    // join: fused aggregation+gemm2 needs both CSR and y1/yr
    cudaStreamWaitEvent(0, ev_join, 0);
    k_aggr_gemm2<<<N_PAD / 128, 512, FUSED_SMEM>>>(b1);
    k_final<<<(N_NODES * 32 + 255) / 256, 256>>>(b2, out);
}

// round 16
// speedup vs baseline: 1.0860x; 1.0860x over previous
#include <cuda_runtime.h>
#include <cuda_fp16.h>
#include <mma.h>
#include <math.h>
#include <cstdint>

using namespace nvcuda;

#define N_NODES 100000
#define N_EDGES 1600000
#define N_PAD 100096                          // 782*128
#define N_TILES 782
#define NB_SCAN ((N_NODES + 1023) / 1024)     // 98

#define TS 136                                // smem A/W tile stride (fp16 elems)
#define T2S 80                                // smem W2 tile stride (160B rows)
#define TILE_ELEMS (128 * TS)                 // 17408

// gemm1 smem: AH, WH0, WH1 (3 x 128x136 fp16) + 64KB fp32 staging
#define GEMM1_SMEM (3 * TILE_ELEMS * 2 + 16 * 1024 * 4)
// fused smem: AH (128x136 fp16) + W2H (128x80 fp16)
#define FUSED_SMEM ((TILE_ELEMS + 128 * T2S) * 2)

// -------- scratch (static __device__ globals; no runtime alloc) ----------
__device__ int    g_is64;
__device__ int    g_degi[N_NODES];
__device__ int    g_cursor[N_NODES];          // initialized to rowstart by k_scan
__device__ int    g_rowstart[N_NODES + 1];
__device__ unsigned long long g_part[NB_SCAN];// lookback: (state<<32)|value
__device__ int    g_csrc[N_EDGES];
__device__ __half g_y1h[(size_t)N_PAD * 128]; // x @ Wl1  (fp16)
__device__ __half g_yrh[(size_t)N_PAD * 128]; // x @ Wr1  (fp16)
__device__ __half g_pqh[(size_t)N_PAD * 80];  // [p(40) | q(40)] per node (fp16)
// precomputed fp16 weights
__device__ __half g_wl1h[16384];
__device__ __half g_wr1h[16384];
__device__ __half g_w2h[10240];               // [Wl2|Wr2] 128x80

// ---------- init: zero degi + lookback state + dtype detect (fast, uniform) ----------
__global__ __launch_bounds__(1024) void k_init(const int* __restrict__ ei32) {
    int i = blockIdx.x * 1024 + threadIdx.x;
    if (i < N_NODES) g_degi[i] = 0;
    if (i < NB_SCAN) g_part[i] = 0ULL;
    if (i == 0) g_rowstart[N_NODES] = N_EDGES;
    if (blockIdx.x == 0) {
        __shared__ int nz;
        if (threadIdx.x == 0) nz = 0;
        __syncthreads();
        if (threadIdx.x < 256 && ei32[2 * threadIdx.x + 1] != 0) atomicAdd(&nz, 1);
        __syncthreads();
        if (threadIdx.x == 0) g_is64 = (nz == 0) ? 1 : 0;
    }
}

// ---------- weight conversion (side stream, off the CSR critical path) ----------
__global__ __launch_bounds__(1024) void k_prep_w(
    const float* __restrict__ Wl1, const float* __restrict__ Wr1,
    const float* __restrict__ Wl2, const float* __restrict__ Wr2) {
    int i = blockIdx.x * 1024 + threadIdx.x;
    if (i < 16384) {
        g_wl1h[i] = __float2half_rn(Wl1[i]);
        g_wr1h[i] = __float2half_rn(Wr1[i]);
    } else if (i < 16384 + 10240) {
        int k = i - 16384;
        int r = k / 80, j = k % 80;
        float v = (j < 40) ? Wl2[r * 40 + j] : Wr2[r * 40 + (j - 40)];
        g_w2h[k] = __float2half_rn(v);
    }
}

// -------------------- CSR build --------------------

__global__ void k_count(const void* __restrict__ ei) {
    int idx = blockIdx.x * blockDim.x + threadIdx.x;
    int stride = gridDim.x * blockDim.x;
    if (g_is64) {
        const longlong2* p = (const longlong2*)((const long long*)ei + N_EDGES);
        for (int i = idx; i < N_EDGES / 2; i += stride) {
            longlong2 v = p[i];
            atomicAdd(&g_degi[(int)v.x], 1);
            atomicAdd(&g_degi[(int)v.y], 1);
        }
    } else {
        const int4* p = (const int4*)((const int*)ei + N_EDGES);
        for (int i = idx; i < N_EDGES / 4; i += stride) {
            int4 v = p[i];
            atomicAdd(&g_degi[v.x], 1);
            atomicAdd(&g_degi[v.y], 1);
            atomicAdd(&g_degi[v.z], 1);
            atomicAdd(&g_degi[v.w], 1);
        }
    }
}

// single-launch exclusive scan with WARP-PARALLEL decoupled lookback.
// 98 blocks <= 148 SMs: all co-resident, spin cannot deadlock.
__global__ __launch_bounds__(1024) void k_scan() {
    __shared__ int wsum[32];
    __shared__ int s_total, s_prefix;
    int bid = blockIdx.x;
    int i = bid * 1024 + threadIdx.x;
    int lane = threadIdx.x & 31, wid = threadIdx.x >> 5;
    int v = (i < N_NODES) ? g_degi[i] : 0;
    int pre = v;
#pragma unroll
    for (int o = 1; o < 32; o <<= 1) {
        int t = __shfl_up_sync(0xffffffffu, pre, o);
        if (lane >= o) pre += t;
    }
    if (lane == 31) wsum[wid] = pre;
    __syncthreads();
    if (wid == 0) {
        int w = wsum[lane];
        int p = w;
#pragma unroll
        for (int o = 1; o < 32; o <<= 1) {
            int t = __shfl_up_sync(0xffffffffu, p, o);
            if (lane >= o) p += t;
        }
        wsum[lane] = p - w;
        if (lane == 31) s_total = p;
    }
    __syncthreads();

    if (wid == 0) {
        int total = s_total;
        if (bid == 0) {
            if (lane == 0) {
                atomicExch(&g_part[0], (2ULL << 32) | (unsigned)total);
                s_prefix = 0;
            }
        } else {
            if (lane == 0) atomicExch(&g_part[bid], (1ULL << 32) | (unsigned)total);
            int run = 0;
            int base = bid;                       // window: [base-32, base)
            while (true) {
                int j = base - 32 + lane;
                unsigned long long w = (j >= 0) ? atomicAdd(&g_part[j], 0ULL)
                                                : (2ULL << 32);
                unsigned st = (unsigned)(w >> 32);
                if (__ballot_sync(0xffffffffu, st != 0) != 0xffffffffu)
                    continue;                     // some predecessor unpublished; repoll
                unsigned b2 = __ballot_sync(0xffffffffu, st == 2);
                if (b2) {
                    int hl = 31 - __clz(b2);      // nearest inclusive-prefix lane
                    int val = (lane >= hl && j >= 0) ? (int)(w & 0xFFFFFFFFULL) : 0;
                    run += __reduce_add_sync(0xffffffffu, val);
                    break;
                } else {
                    int val = (j >= 0) ? (int)(w & 0xFFFFFFFFULL) : 0;
                    run += __reduce_add_sync(0xffffffffu, val);
                    base -= 32;
                }
            }
            if (lane == 0) {
                s_prefix = run;
                atomicExch(&g_part[bid], (2ULL << 32) | (unsigned)(run + total));
            }
        }
    }
    __syncthreads();

    if (i < N_NODES) {
        int base = s_prefix + pre - v + wsum[wid];
        g_rowstart[i] = base;
        g_cursor[i] = base;
    }
}

__global__ void k_fill(const void* __restrict__ ei) {
    int idx = blockIdx.x * blockDim.x + threadIdx.x;
    int stride = gridDim.x * blockDim.x;
    if (g_is64) {
        const longlong2* ps = (const longlong2*)ei;
        const longlong2* pd = (const longlong2*)((const long long*)ei + N_EDGES);
        for (int i = idx; i < N_EDGES / 2; i += stride) {
            longlong2 s = ps[i];
            longlong2 d = pd[i];
            g_csrc[atomicAdd(&g_cursor[(int)d.x], 1)] = (int)s.x;
            g_csrc[atomicAdd(&g_cursor[(int)d.y], 1)] = (int)s.y;
        }
    } else {
        const int4* ps = (const int4*)ei;
        const int4* pd = (const int4*)((const int*)ei + N_EDGES);
        for (int i = idx; i < N_EDGES / 4; i += stride) {
            int4 s = ps[i];
            int4 d = pd[i];
            g_csrc[atomicAdd(&g_cursor[d.x], 1)] = s.x;
            g_csrc[atomicAdd(&g_cursor[d.y], 1)] = s.y;
            g_csrc[atomicAdd(&g_cursor[d.z], 1)] = s.z;
            g_csrc[atomicAdd(&g_cursor[d.w], 1)] = s.w;
        }
    }
}

// ============ helpers ============

template <int NTHREADS>
__device__ __forceinline__ void conv_tile_h(const float* __restrict__ src, int row0,
                                            __half* H, int tid) {
    for (int g = tid; g < 4096; g += NTHREADS) {
        int row = g >> 5, c4 = g & 31;
        int r = row0 + row;
        if (r >= N_NODES) r = N_NODES - 1;
        float4 v = ((const float4*)(src + (size_t)r * 128))[c4];
        __half2 h0 = __floats2half2_rn(v.x, v.y);
        __half2 h1 = __floats2half2_rn(v.z, v.w);
        *(uint2*)(H + row * TS + c4 * 4) = make_uint2(*(uint32_t*)&h0, *(uint32_t*)&h1);
    }
}

// ============ GEMM 1 (persistent, fp16 single-pass): y1 = x@Wl1, yr = x@Wr1 ============

__global__ __launch_bounds__(512) void k_gemm1(const float* __restrict__ x) {
    extern __shared__ __half sm[];
    __half* AH  = sm;
    __half* WH0 = sm + TILE_ELEMS;
    __half* WH1 = sm + 2 * TILE_ELEMS;
    float* staging = (float*)(sm + 3 * TILE_ELEMS);

    int tid = threadIdx.x;
    int wid = tid >> 5, lane = tid & 31;

    // copy fp16 weights into padded smem ONCE (one uint4 = 8 halves)
    {
        const __half* srcs[2] = {g_wl1h, g_wr1h};
        __half* dsts[2] = {WH0, WH1};
#pragma unroll
        for (int tgt = 0; tgt < 2; tgt++) {
            const uint4* s = (const uint4*)srcs[tgt];
            for (int g = tid; g < 2048; g += 512) {   // 128 rows x 16 uint4
                int row = g >> 4, c = g & 15;
                *(uint4*)(dsts[tgt] + row * TS + c * 8) = s[row * 16 + c];
            }
        }
    }

    int out_sel = wid >> 3;          // 0: y1, 1: yr
    int w = wid & 7;
    int wm = w & 3;                  // rows wm*32
    int wn = w >> 2;                 // cols wn*64
    const __half* WH = out_sel ? WH1 : WH0;
    __half* dstbase = out_sel ? g_yrh : g_y1h;
    float* eb = staging + (size_t)wid * 1024;   // 16x64 fp32 per warp

    for (int tile = blockIdx.x; tile < N_TILES; tile += gridDim.x) {
        int node0 = tile * 128;
        conv_tile_h<512>(x, node0, AH, tid);
        __syncthreads();

        wmma::fragment<wmma::accumulator, 16, 16, 16, float> C[2][4];
#pragma unroll
        for (int i = 0; i < 2; i++)
#pragma unroll
            for (int j = 0; j < 4; j++) wmma::fill_fragment(C[i][j], 0.0f);

#pragma unroll
        for (int k0 = 0; k0 < 8; k0++) {
            wmma::fragment<wmma::matrix_a, 16, 16, 16, __half, wmma::row_major> ah[2];
#pragma unroll
            for (int i = 0; i < 2; i++)
                wmma::load_matrix_sync(ah[i], AH + (wm * 32 + i * 16) * TS + k0 * 16, TS);
#pragma unroll
            for (int j = 0; j < 4; j++) {
                wmma::fragment<wmma::matrix_b, 16, 16, 16, __half, wmma::row_major> bh;
                wmma::load_matrix_sync(bh, WH + (k0 * 16) * TS + wn * 64 + j * 16, TS);
#pragma unroll
                for (int i = 0; i < 2; i++)
                    wmma::mma_sync(C[i][j], ah[i], bh, C[i][j]);
            }
        }

        // epilogue: per warp stage 16x64 fp32 at a time, convert to fp16, store
#pragma unroll
        for (int i = 0; i < 2; i++) {
#pragma unroll
            for (int j = 0; j < 4; j++)
                wmma::store_matrix_sync(eb + j * 16, C[i][j], 64, wmma::mem_row_major);
            __syncwarp();
            for (int e = lane; e < 512; e += 32) {    // 16 rows x 32 half2
                int r = e >> 5, c2 = e & 31;
                float2 v = ((const float2*)eb)[e];
                __half2 hv = __floats2half2_rn(v.x, v.y);
                *(__half2*)(dstbase + (size_t)(node0 + wm * 32 + i * 16 + r) * 128
                            + wn * 64 + c2 * 2) = hv;
            }
            __syncwarp();
        }
        __syncthreads();   // A reads done before next tile's conv overwrites
    }
}

// ====== FUSED: h = relu(mean-gather(y1) + yr + b1)  ->  pq = h @ [Wl2|Wr2] ======

__global__ __launch_bounds__(512) void k_aggr_gemm2(const float* __restrict__ b1) {
    extern __shared__ __half sm[];
    __half* AH  = sm;
    __half* W2H = sm + TILE_ELEMS;

    int tid = threadIdx.x;
    int wid = tid >> 5, lane = tid & 31;
    int node0 = blockIdx.x * 128;

    // copy W2 fp16 (128x80) into smem
    {
        const uint4* sh = (const uint4*)g_w2h;
        for (int g = tid; g < 1280; g += 512) {   // 128 rows x 10 uint4
            int row = g / 10, c = g % 10;
            *(uint4*)(W2H + row * T2S + c * 8) = sh[row * 10 + c];
        }
    }

    // ---- Phase A: gather (y1 fp16) + relu, fp16 into smem ----
    float4 bb = *(const float4*)(b1 + lane * 4);
#pragma unroll
    for (int i = 0; i < 8; i++) {
        int nl = wid * 8 + i;
        int node = node0 + nl;
        float4 h4 = make_float4(0.f, 0.f, 0.f, 0.f);
        if (node < N_NODES) {
            int rs = g_rowstart[node], re = g_rowstart[node + 1];
            float4 acc = make_float4(0.f, 0.f, 0.f, 0.f);
            for (int i0 = rs; i0 < re; i0 += 32) {
                int nv = min(32, re - i0);
                int s = (lane < nv) ? g_csrc[i0 + lane] : 0;
                int j = 0;
                for (; j + 8 <= nv; j += 8) {
                    uint2 u[8];
#pragma unroll
                    for (int t = 0; t < 8; t++) {
                        int sj = __shfl_sync(0xffffffffu, s, j + t);
                        u[t] = *(const uint2*)(g_y1h + (size_t)sj * 128 + lane * 4);
                    }
#pragma unroll
                    for (int t = 0; t < 8; t++) {
                        float2 a = __half22float2(*(const __half2*)&u[t].x);
                        float2 b = __half22float2(*(const __half2*)&u[t].y);
                        acc.x += a.x; acc.y += a.y; acc.z += b.x; acc.w += b.y;
                    }
                }
                for (; j < nv; j++) {
                    int sj = __shfl_sync(0xffffffffu, s, j);
                    uint2 u = *(const uint2*)(g_y1h + (size_t)sj * 128 + lane * 4);
                    float2 a = __half22float2(*(const __half2*)&u.x);
                    float2 b = __half22float2(*(const __half2*)&u.y);
                    acc.x += a.x; acc.y += a.y; acc.z += b.x; acc.w += b.y;
                }
            }
            float inv = 1.0f / fmaxf((float)(re - rs), 1.0f);
            uint2 uyr = *(const uint2*)(g_yrh + (size_t)node * 128 + lane * 4);
            float2 ya = __half22float2(*(const __half2*)&uyr.x);
            float2 yb = __half22float2(*(const __half2*)&uyr.y);
            h4.x = fmaxf(acc.x * inv + ya.x + bb.x, 0.f);
            h4.y = fmaxf(acc.y * inv + ya.y + bb.y, 0.f);
            h4.z = fmaxf(acc.z * inv + yb.x + bb.z, 0.f);
            h4.w = fmaxf(acc.w * inv + yb.y + bb.w, 0.f);
        }
        __half2 h0 = __floats2half2_rn(h4.x, h4.y);
        __half2 h1 = __floats2half2_rn(h4.z, h4.w);
        *(uint2*)(AH + nl * TS + lane * 4) = make_uint2(*(uint32_t*)&h0, *(uint32_t*)&h1);
    }
    __syncthreads();

    // ---- Phase B: wmma gemm2 (single-pass fp16) ----
    int rblk = wid & 7;                 // rows rblk*16 .. +15
    int j0   = (wid < 8) ? 0 : 3;       // col frags {0,1,2} or {3,4}
    int nj   = (wid < 8) ? 3 : 2;

    wmma::fragment<wmma::accumulator, 16, 16, 16, float> C[3];
#pragma unroll
    for (int j = 0; j < 3; j++) wmma::fill_fragment(C[j], 0.0f);

#pragma unroll
    for (int k0 = 0; k0 < 8; k0++) {
        wmma::fragment<wmma::matrix_a, 16, 16, 16, __half, wmma::row_major> ah;
        wmma::load_matrix_sync(ah, AH + (rblk * 16) * TS + k0 * 16, TS);
        for (int j = 0; j < nj; j++) {
            wmma::fragment<wmma::matrix_b, 16, 16, 16, __half, wmma::row_major> bh;
            wmma::load_matrix_sync(bh, W2H + (k0 * 16) * T2S + (j0 + j) * 16, T2S);
            wmma::mma_sync(C[j], ah, bh, C[j]);
        }
    }
    __syncthreads();   // AH/W2H reads done -> reuse as fp32 staging

    // ---- epilogue: stage fp32 pq (128x80) in smem, convert to fp16 ----
    float* stage = (float*)sm;
    for (int j = 0; j < nj; j++)
        wmma::store_matrix_sync(stage + (rblk * 16) * 80 + (j0 + j) * 16, C[j],
                                80, wmma::mem_row_major);
    __syncthreads();
    for (int g = tid; g < 5120; g += 512) {   // 128 rows x 40 half2
        int row = g / 40, c2 = g % 40;
        float2 v = ((const float2*)stage)[g];
        __half2 hv = __floats2half2_rn(v.x, v.y);
        *(__half2*)(g_pqh + (size_t)(node0 + row) * 80 + c2 * 2) = hv;
    }
}

// ---------- layer-2 aggregation + bias + log_softmax ----------

__global__ void k_final(const float* __restrict__ b2, float* __restrict__ out) {
    int warp = (blockIdx.x * blockDim.x + threadIdx.x) >> 5;
    if (warp >= N_NODES) return;
    int lane = threadIdx.x & 31;
    int g  = lane / 10;          // 0,1,2 (lanes 30,31 idle)
    int gl = lane % 10;
    bool active = lane < 30;
    int rs = g_rowstart[warp], re = g_rowstart[warp + 1];
    float acc[4] = {0.f, 0.f, 0.f, 0.f};

    for (int i0 = rs; i0 < re; i0 += 32) {
        int nv = min(32, re - i0);
        int s = (lane < nv) ? g_csrc[i0 + lane] : 0;
        for (int j = 0; j < nv; j += 6) {
            int e0 = j + g, e1 = j + 3 + g;
            int src0 = __shfl_sync(0xffffffffu, s, (e0 < nv) ? e0 : 0);
            int src1 = __shfl_sync(0xffffffffu, s, (e1 < nv) ? e1 : 0);
            bool v0 = active && (e0 < nv);
            bool v1 = active && (e1 < nv);
            uint2 u0 = v0 ? *(const uint2*)(g_pqh + (size_t)src0 * 80 + gl * 4)
                          : make_uint2(0u, 0u);
            uint2 u1 = v1 ? *(const uint2*)(g_pqh + (size_t)src1 * 80 + gl * 4)
                          : make_uint2(0u, 0u);
            float2 a0 = __half22float2(*(const __half2*)&u0.x);
            float2 b0 = __half22float2(*(const __half2*)&u0.y);
            float2 a1 = __half22float2(*(const __half2*)&u1.x);
            float2 b1 = __half22float2(*(const __half2*)&u1.y);
            acc[0] += a0.x + a1.x;
            acc[1] += a0.y + a1.y;
            acc[2] += b0.x + b1.x;
            acc[3] += b0.y + b1.y;
        }
    }

#pragma unroll
    for (int k = 0; k < 4; k++) {
        float t1 = __shfl_sync(0xffffffffu, acc[k], (lane + 10) & 31);
        float t2 = __shfl_sync(0xffffffffu, acc[k], (lane + 20) & 31);
        acc[k] += t1 + t2;           // valid for lane < 10
    }

    float inv = 1.0f / fmaxf((float)(re - rs), 1.0f);
    float v0f, v1f, v2f, v3f;
    if (lane < 10) {
        uint2 uq = *(const uint2*)(g_pqh + (size_t)warp * 80 + 40 + gl * 4);
        float2 qa = __half22float2(*(const __half2*)&uq.x);
        float2 qb = __half22float2(*(const __half2*)&uq.y);
        float4 bbv = *(const float4*)(b2 + gl * 4);
        v0f = acc[0] * inv + bbv.x + qa.x;
        v1f = acc[1] * inv + bbv.y + qa.y;
        v2f = acc[2] * inv + bbv.z + qb.x;
        v3f = acc[3] * inv + bbv.w + qb.y;
    } else {
        v0f = v1f = v2f = v3f = -INFINITY;
    }

    float mx = fmaxf(fmaxf(v0f, v1f), fmaxf(v2f, v3f));
#pragma unroll
    for (int o = 16; o; o >>= 1) mx = fmaxf(mx, __shfl_xor_sync(0xffffffffu, mx, o));
    float se = 0.f;
    if (lane < 10)
        se = expf(v0f - mx) + expf(v1f - mx) + expf(v2f - mx) + expf(v3f - mx);
#pragma unroll
    for (int o = 16; o; o >>= 1) se += __shfl_xor_sync(0xffffffffu, se, o);
    float lse = logf(se);

    if (lane < 10) {
        float4 o4 = make_float4(v0f - mx - lse, v1f - mx - lse,
                                v2f - mx - lse, v3f - mx - lse);
        *(float4*)(out + (size_t)warp * 40 + gl * 4) = o4;
    }
}

// -------------------- launch --------------------

extern "C" void kernel_launch(void* const* d_in, const int* in_sizes, int n_in,
                              void* d_out, int out_size) {
    const float* x       = (const float*)d_in[0];
    const void*  ei      = d_in[1];
    const float* Wl1     = (const float*)d_in[2];
    const float* b1      = (const float*)d_in[3];
    const float* Wr1     = (const float*)d_in[4];
    const float* Wl2     = (const float*)d_in[5];
    const float* b2      = (const float*)d_in[6];
    const float* Wr2     = (const float*)d_in[7];
    float* out           = (float*)d_out;

    cudaFuncSetAttribute(k_gemm1, cudaFuncAttributeMaxDynamicSharedMemorySize, GEMM1_SMEM);
    cudaFuncSetAttribute(k_aggr_gemm2, cudaFuncAttributeMaxDynamicSharedMemorySize, FUSED_SMEM);

    // side stream + fork/join events (created once; deterministic work per call)
    static cudaStream_t s2 = nullptr;
    static cudaEvent_t ev_fork = nullptr, ev_join = nullptr;
    if (!s2) {
        cudaStreamCreateWithFlags(&s2, cudaStreamNonBlocking);
        cudaEventCreateWithFlags(&ev_fork, cudaEventDisableTiming);
        cudaEventCreateWithFlags(&ev_join, cudaEventDisableTiming);
    }

    // fork immediately: side stream converts weights then runs gemm1,
    // fully off the CSR critical path.
    cudaEventRecord(ev_fork, 0);
    cudaStreamWaitEvent(s2, ev_fork, 0);
    k_prep_w<<<26, 1024, 0, s2>>>(Wl1, Wr1, Wl2, Wr2);
    k_gemm1<<<148, 512, GEMM1_SMEM, s2>>>(x);
    cudaEventRecord(ev_join, s2);

    // main stream: CSR build chain
    k_init<<<NB_SCAN, 1024>>>((const int*)ei);
    k_count<<<1563, 256>>>(ei);
    k_scan<<<NB_SCAN, 1024>>>();
    k_fill<<<1563, 256>>>(ei);

    // join: fused aggregation+gemm2 needs both CSR and y1/yr (+ w2h)
    cudaStreamWaitEvent(0, ev_join, 0);
    k_aggr_gemm2<<<N_PAD / 128, 512, FUSED_SMEM>>>(b1);
    k_final<<<(N_NODES * 32 + 255) / 256, 256>>>(b2, out);
}